// round 10
// baseline (speedup 1.0000x reference)
#include <cuda_runtime.h>

// KREmbedding: Gaussian-weighted context embedding aggregation.
// context: [B, C] int32, center: [B] int32, W: [V, D] float32 -> out [B, D] float32
// B=8192, C=32, D=512, SIGMA=1.0
//
// Round 10: lazy accumulator init + packed f32x2 distance math.
//   Bound (unchanged): expf(-d2/2)==0.0f exactly when d2>~208 (fp32
//   underflow); per-row 160-element partial (float4 + scalar per lane),
//   fixed-point floor(min(p,60000)*1024) -> redux.sync.add.s32 -> warp-uniform
//   S <= 1024*d2; S > 220*1024 proves w==0.0f in the reference (survival ~0.3%).
//   NEW: s_acc slices are zeroed lazily inside the cold path on first use
//   (per-warp smem flag); the ~99% of pairs with no survivors skip the smem
//   init AND the epilogue combine entirely and store zeros directly.
//   NEW: partial distances use add/mul/fma.rn.f32x2 (2 fp32 lanes per instr,
//   per-half IEEE-rn -> bitwise identical partials, proof intact).

#define KB_B 8192
#define KB_C 32
#define KB_D 512
#define NTHREADS 128            // 4 warps = 2 batch rows per block
#define ROWS_PER_WARP 16
#define T_INT (220 * 1024)
#define ROW_BYTES (KB_D * 4)    // 2048; idx*2048 fits in 32 bits (V=50000)

typedef unsigned long long u64;

#define PACK2(out, lo, hi) \
    asm("mov.b64 %0, {%1, %2};" : "=l"(out) : "f"(lo), "f"(hi))
#define UNPACK2(lo, hi, in) \
    asm("mov.b64 {%0, %1}, %2;" : "=f"(lo), "=f"(hi) : "l"(in))
#define ADDX2(out, a, b) \
    asm("add.rn.f32x2 %0, %1, %2;" : "=l"(out) : "l"(a), "l"(b))
#define MULX2(out, a, b) \
    asm("mul.rn.f32x2 %0, %1, %2;" : "=l"(out) : "l"(a), "l"(b))
#define FMAX2(out, a, b, c) \
    asm("fma.rn.f32x2 %0, %1, %2, %3;" : "=l"(out) : "l"(a), "l"(b), "l"(c))

__device__ __forceinline__ float warp_sum(float v) {
#pragma unroll
    for (int off = 16; off; off >>= 1)
        v += __shfl_xor_sync(0xffffffffu, v, off);
    return v;
}

__device__ __forceinline__ float quarter_d2(float4 r, float4 c) {
    float dx = r.x - c.x, dy = r.y - c.y, dz = r.z - c.z, dw = r.w - c.w;
    float d = dx * dx;
    d = fmaf(dy, dy, d);
    d = fmaf(dz, dz, d);
    d = fmaf(dw, dw, d);
    return d;
}

__device__ __forceinline__ int bound_int(float p) {
    return __float2int_rd(fminf(p, 60000.f) * 1024.f);   // floor -> lower bound
}

// Cold path: warp-uniform entry, ~0.3% of rows. Exact full fp32 distance from
// L1-hot data, then exp + accumulate. 256-element REDUX bound prunes first.
// Zeroes this warp's acc slice on first actual accumulation (lazy init).
__device__ __noinline__ float slow_path(const float4* __restrict__ rowp,
                                        const float4* __restrict__ cenp,
                                        float4 cen0, int lane,
                                        float4* __restrict__ sacc,
                                        int* __restrict__ flag)
{
    const float4 r1   = __ldg(&rowp[lane + 32]);
    const float4 cen1 = __ldg(&cenp[lane + 32]);
    const float4 r0   = __ldg(&rowp[lane]);
    const float pa  = quarter_d2(r0, cen0) + quarter_d2(r1, cen1);
    const int s2 = __reduce_add_sync(0xffffffffu, bound_int(pa));
    if (s2 > T_INT) return 0.f;                    // provably w == 0.0f

    // lazy init of this warp's accumulator slice (warp-uniform path)
    if (*flag == 0) {
#pragma unroll
        for (int i = 0; i < 4; i++)
            sacc[lane + 32 * i] = make_float4(0.f, 0.f, 0.f, 0.f);
        if (lane == 0) *flag = 1;
        __syncwarp();
    }

    const float4 cen2 = __ldg(&cenp[lane + 64]);
    const float4 cen3 = __ldg(&cenp[lane + 96]);
    const float4 r2   = __ldg(&rowp[lane + 64]);
    const float4 r3   = __ldg(&rowp[lane + 96]);
    const float t  = warp_sum(pa);
    const float d2 = t + warp_sum(quarter_d2(r2, cen2) + quarter_d2(r3, cen3));

    const float e = __expf(-0.5f * d2);

    float4 a;
    a = sacc[lane];
    a.x = fmaf(e, r0.x, a.x); a.y = fmaf(e, r0.y, a.y);
    a.z = fmaf(e, r0.z, a.z); a.w = fmaf(e, r0.w, a.w);
    sacc[lane] = a;
    a = sacc[lane + 32];
    a.x = fmaf(e, r1.x, a.x); a.y = fmaf(e, r1.y, a.y);
    a.z = fmaf(e, r1.z, a.z); a.w = fmaf(e, r1.w, a.w);
    sacc[lane + 32] = a;
    a = sacc[lane + 64];
    a.x = fmaf(e, r2.x, a.x); a.y = fmaf(e, r2.y, a.y);
    a.z = fmaf(e, r2.z, a.z); a.w = fmaf(e, r2.w, a.w);
    sacc[lane + 64] = a;
    a = sacc[lane + 96];
    a.x = fmaf(e, r3.x, a.x); a.y = fmaf(e, r3.y, a.y);
    a.z = fmaf(e, r3.z, a.z); a.w = fmaf(e, r3.w, a.w);
    sacc[lane + 96] = a;
    return e;
}

__global__ __launch_bounds__(NTHREADS, 9)
void kre_kernel(const int* __restrict__ context,
                const int* __restrict__ center,
                const float* __restrict__ W,
                float* __restrict__ out)
{
    const int tid  = threadIdx.x;
    const int lane = tid & 31;
    const int wid  = tid >> 5;
    const int b    = blockIdx.x * 2 + (wid >> 1);  // 2 warps per batch row
    const int half = wid & 1;                      // which 16 context rows

    __shared__ float4 s_acc[4][KB_D / 4];          // per-warp slices (8 KB)
    __shared__ float  s_esum[4];
    __shared__ int    s_flag[4];
    float4* sacc = s_acc[wid];
    if (lane == 0) s_flag[wid] = 0;                // only block-wide init needed

    const int my_idx  = __ldg(&context[b * KB_C + half * 16 + (lane & 15)]);
    const int cen_idx = __ldg(&center[b]);
    const char* Wb = reinterpret_cast<const char*>(W);
    const char* cenb = Wb + (unsigned)cen_idx * ROW_BYTES;
    const float4* cenp = reinterpret_cast<const float4*>(cenb);
    const float4  cen0 = __ldg(&cenp[lane]);
    const float   cen4 = __ldg(reinterpret_cast<const float*>(cenb) + 128 + lane);

    // pre-negated packed center halves for packed subtract (add of -c; exact)
    u64 nc01, nc23;
    PACK2(nc01, -cen0.x, -cen0.y);
    PACK2(nc23, -cen0.z, -cen0.w);

    float esum = 0.f;

    // ---- single flat 16-row pipelined bound pass (packed f32x2 math) ----
    int s[ROWS_PER_WARP];
#pragma unroll
    for (int k = 0; k < ROWS_PER_WARP; k++) {
        const int idx = __shfl_sync(0xffffffffu, my_idx, k);
        const char* rowb = Wb + (unsigned)idx * ROW_BYTES;
        const float4 r  = __ldg(reinterpret_cast<const float4*>(rowb) + lane);
        const float  r4 = __ldg(reinterpret_cast<const float*>(rowb) + 128 + lane);

        u64 r01, r23, d01, d23, p2;
        PACK2(r01, r.x, r.y);
        PACK2(r23, r.z, r.w);
        ADDX2(d01, r01, nc01);          // r - c (two lanes at once)
        ADDX2(d23, r23, nc23);
        MULX2(p2, d01, d01);            // d01^2
        FMAX2(p2, d23, d23, p2);        // + d23^2
        float plo, phi;
        UNPACK2(plo, phi, p2);

        const float dx = r4 - cen4;
        const float p  = fmaf(dx, dx, plo + phi);   // 160-elem partial
        s[k] = __reduce_add_sync(0xffffffffu, bound_int(p));
    }

    // min-fold: one branch for all 16 rows in the common case
    int smin = s[0];
#pragma unroll
    for (int k = 1; k < ROWS_PER_WARP; k++) smin = min(smin, s[k]);

    if (smin <= T_INT) {                            // rare (~4% of warps)
#pragma unroll
        for (int k = 0; k < ROWS_PER_WARP; k++) {
            if (s[k] <= T_INT) {
                const int idx = __shfl_sync(0xffffffffu, my_idx, k);
                const float4* rowp =
                    reinterpret_cast<const float4*>(Wb + (unsigned)idx * ROW_BYTES);
                esum += slow_path(rowp, cenp, cen0, lane, sacc, &s_flag[wid]);
            }
        }
    }

    if (lane == 0) s_esum[wid] = esum;
    __syncthreads();

    // pair combine: warps {0,1} -> b0, warps {2,3} -> b1; 64 lanes per pair
    const int pair  = tid >> 6;
    const int ptid  = tid & 63;
    const int b_out = blockIdx.x * 2 + pair;
    const int f0 = s_flag[pair * 2];
    const int f1 = s_flag[pair * 2 + 1];

    float4* op = reinterpret_cast<float4*>(out + (size_t)b_out * KB_D);

    if ((f0 | f1) == 0) {
        // common case: no survivors in either half -> output is exactly 0
        const float4 z = make_float4(0.f, 0.f, 0.f, 0.f);
#pragma unroll
        for (int i = 0; i < 2; i++)
            __stcs(&op[ptid + 64 * i], z);
    } else {
        const float inv = 1.0f / (s_esum[pair * 2] + s_esum[pair * 2 + 1] + 1e-8f);
#pragma unroll
        for (int i = 0; i < 2; i++) {
            const int j = ptid + 64 * i;
            float4 v = make_float4(0.f, 0.f, 0.f, 0.f);
            if (f0) {
                const float4 a0 = s_acc[pair * 2][j];
                v.x += a0.x; v.y += a0.y; v.z += a0.z; v.w += a0.w;
            }
            if (f1) {
                const float4 a1 = s_acc[pair * 2 + 1][j];
                v.x += a1.x; v.y += a1.y; v.z += a1.z; v.w += a1.w;
            }
            v.x *= inv; v.y *= inv; v.z *= inv; v.w *= inv;
            __stcs(&op[j], v);
        }
    }
}

extern "C" void kernel_launch(void* const* d_in, const int* in_sizes, int n_in,
                              void* d_out, int out_size)
{
    const int* context = (const int*)d_in[0];
    const int* center  = (const int*)d_in[1];
    const float* W     = (const float*)d_in[2];
    for (int i = 0; i < n_in; i++) {
        if (in_sizes[i] == KB_B * KB_C)      context = (const int*)d_in[i];
        else if (in_sizes[i] == KB_B)        center  = (const int*)d_in[i];
        else if (in_sizes[i] > KB_B * KB_C)  W       = (const float*)d_in[i];
    }
    float* out = (float*)d_out;
    kre_kernel<<<KB_B / 2, NTHREADS>>>(context, center, W, out);
}

// round 11
// speedup vs baseline: 1.0598x; 1.0598x over previous
#include <cuda_runtime.h>

// KREmbedding: Gaussian-weighted context embedding aggregation.
// context: [B, C] int32, center: [B] int32, W: [V, D] float32 -> out [B, D] float32
// B=8192, C=32, D=512, SIGMA=1.0
//
// Round 11 = Round 9 (best: 16.8us) + ONE isolated change: lazy accumulator.
//   Bound (unchanged): expf(-d2/2)==0.0f exactly when d2>~208 (fp32
//   underflow); per-row 160-element partial (float4 + scalar per lane),
//   fixed-point floor(min(p,60000)*1024), one redux.sync.add.s32 ->
//   warp-uniform S <= 1024*d2; S > 220*1024 proves w==0.0f in the fp32
//   reference too (survival ~0.3%). 16 rows in one flat pipelined loop,
//   single min-folded survivor branch.
//   NEW: s_acc slices zeroed lazily on first survivor (per-warp smem flag);
//   pairs with no survivors (~90%) skip smem init AND epilogue combine,
//   storing exact zeros directly. Hot-loop math/scheduling untouched vs R9.

#define KB_B 8192
#define KB_C 32
#define KB_D 512
#define NTHREADS 128            // 4 warps = 2 batch rows per block
#define ROWS_PER_WARP 16
#define T_INT (220 * 1024)
#define ROW_BYTES (KB_D * 4)    // 2048; idx*2048 fits in 32 bits (V=50000)

__device__ __forceinline__ float warp_sum(float v) {
#pragma unroll
    for (int off = 16; off; off >>= 1)
        v += __shfl_xor_sync(0xffffffffu, v, off);
    return v;
}

__device__ __forceinline__ float quarter_d2(float4 r, float4 c) {
    float dx = r.x - c.x, dy = r.y - c.y, dz = r.z - c.z, dw = r.w - c.w;
    float d = dx * dx;
    d = fmaf(dy, dy, d);
    d = fmaf(dz, dz, d);
    d = fmaf(dw, dw, d);
    return d;
}

__device__ __forceinline__ int bound_int(float p) {
    return __float2int_rd(fminf(p, 60000.f) * 1024.f);   // floor -> lower bound
}

// Cold path: warp-uniform entry, ~0.3% of rows. Exact full fp32 distance from
// L1-hot data, then exp + accumulate. 256-element REDUX bound prunes first.
// Lazily zeroes this warp's acc slice on first actual accumulation.
__device__ __noinline__ float slow_path(const float4* __restrict__ rowp,
                                        const float4* __restrict__ cenp,
                                        float4 cen0, int lane,
                                        float4* __restrict__ sacc,
                                        int* __restrict__ flag)
{
    const float4 r1   = __ldg(&rowp[lane + 32]);
    const float4 cen1 = __ldg(&cenp[lane + 32]);
    const float4 r0   = __ldg(&rowp[lane]);
    const float pa  = quarter_d2(r0, cen0) + quarter_d2(r1, cen1);
    const int s2 = __reduce_add_sync(0xffffffffu, bound_int(pa));
    if (s2 > T_INT) return 0.f;                    // provably w == 0.0f

    // lazy init (warp-uniform path; this warp is the only writer of its slice)
    if (*flag == 0) {
#pragma unroll
        for (int i = 0; i < 4; i++)
            sacc[lane + 32 * i] = make_float4(0.f, 0.f, 0.f, 0.f);
        __syncwarp();
        if (lane == 0) *flag = 1;
    }

    const float4 cen2 = __ldg(&cenp[lane + 64]);
    const float4 cen3 = __ldg(&cenp[lane + 96]);
    const float4 r2   = __ldg(&rowp[lane + 64]);
    const float4 r3   = __ldg(&rowp[lane + 96]);
    const float t  = warp_sum(pa);
    const float d2 = t + warp_sum(quarter_d2(r2, cen2) + quarter_d2(r3, cen3));

    const float e = __expf(-0.5f * d2);

    float4 a;
    a = sacc[lane];
    a.x = fmaf(e, r0.x, a.x); a.y = fmaf(e, r0.y, a.y);
    a.z = fmaf(e, r0.z, a.z); a.w = fmaf(e, r0.w, a.w);
    sacc[lane] = a;
    a = sacc[lane + 32];
    a.x = fmaf(e, r1.x, a.x); a.y = fmaf(e, r1.y, a.y);
    a.z = fmaf(e, r1.z, a.z); a.w = fmaf(e, r1.w, a.w);
    sacc[lane + 32] = a;
    a = sacc[lane + 64];
    a.x = fmaf(e, r2.x, a.x); a.y = fmaf(e, r2.y, a.y);
    a.z = fmaf(e, r2.z, a.z); a.w = fmaf(e, r2.w, a.w);
    sacc[lane + 64] = a;
    a = sacc[lane + 96];
    a.x = fmaf(e, r3.x, a.x); a.y = fmaf(e, r3.y, a.y);
    a.z = fmaf(e, r3.z, a.z); a.w = fmaf(e, r3.w, a.w);
    sacc[lane + 96] = a;
    return e;
}

__global__ __launch_bounds__(NTHREADS, 10)
void kre_kernel(const int* __restrict__ context,
                const int* __restrict__ center,
                const float* __restrict__ W,
                float* __restrict__ out)
{
    const int tid  = threadIdx.x;
    const int lane = tid & 31;
    const int wid  = tid >> 5;
    const int b    = blockIdx.x * 2 + (wid >> 1);  // 2 warps per batch row
    const int half = wid & 1;                      // which 16 context rows

    __shared__ float4 s_acc[4][KB_D / 4];          // per-warp slices (8 KB)
    __shared__ float  s_esum[4];
    __shared__ int    s_flag[4];
    float4* sacc = s_acc[wid];
    if (lane == 0) s_flag[wid] = 0;                // tiny init; no acc zeroing

    const int my_idx  = __ldg(&context[b * KB_C + half * 16 + (lane & 15)]);
    const int cen_idx = __ldg(&center[b]);
    const char* Wb = reinterpret_cast<const char*>(W);
    const char* cenb = Wb + (unsigned)cen_idx * ROW_BYTES;
    const float4* cenp = reinterpret_cast<const float4*>(cenb);
    const float4  cen0 = __ldg(&cenp[lane]);
    const float   cen4 = __ldg(reinterpret_cast<const float*>(cenb) + 128 + lane);

    float esum = 0.f;

    // ---- single flat 16-row pipelined bound pass (identical to R9) ----
    int s[ROWS_PER_WARP];
#pragma unroll
    for (int k = 0; k < ROWS_PER_WARP; k++) {
        const int idx = __shfl_sync(0xffffffffu, my_idx, k);
        const char* rowb = Wb + (unsigned)idx * ROW_BYTES;
        const float4 r  = __ldg(reinterpret_cast<const float4*>(rowb) + lane);
        const float  r4 = __ldg(reinterpret_cast<const float*>(rowb) + 128 + lane);
        const float  dx = r4 - cen4;
        const float  p  = fmaf(dx, dx, quarter_d2(r, cen0));    // 160-elem partial
        s[k] = __reduce_add_sync(0xffffffffu, bound_int(p));
    }

    // min-fold: one branch for all 16 rows in the common case
    int smin = s[0];
#pragma unroll
    for (int k = 1; k < ROWS_PER_WARP; k++) smin = min(smin, s[k]);

    if (smin <= T_INT) {                            // rare (~5% of warps)
#pragma unroll
        for (int k = 0; k < ROWS_PER_WARP; k++) {
            if (s[k] <= T_INT) {
                const int idx = __shfl_sync(0xffffffffu, my_idx, k);
                const float4* rowp =
                    reinterpret_cast<const float4*>(Wb + (unsigned)idx * ROW_BYTES);
                esum += slow_path(rowp, cenp, cen0, lane, sacc, &s_flag[wid]);
            }
        }
    }

    if (lane == 0) s_esum[wid] = esum;
    __syncthreads();

    // pair combine: warps {0,1} -> b0, warps {2,3} -> b1; 64 lanes per pair
    const int pair  = tid >> 6;
    const int ptid  = tid & 63;
    const int b_out = blockIdx.x * 2 + pair;
    const int f0 = s_flag[pair * 2];
    const int f1 = s_flag[pair * 2 + 1];

    float4* op = reinterpret_cast<float4*>(out + (size_t)b_out * KB_D);

    if ((f0 | f1) == 0) {
        // common case (~90% of pairs): no survivors -> output exactly 0
        const float4 z = make_float4(0.f, 0.f, 0.f, 0.f);
#pragma unroll
        for (int i = 0; i < 2; i++)
            __stcs(&op[ptid + 64 * i], z);
    } else {
        const float inv = 1.0f / (s_esum[pair * 2] + s_esum[pair * 2 + 1] + 1e-8f);
#pragma unroll
        for (int i = 0; i < 2; i++) {
            const int j = ptid + 64 * i;
            float4 v = make_float4(0.f, 0.f, 0.f, 0.f);
            if (f0) {
                const float4 a0 = s_acc[pair * 2][j];
                v.x += a0.x; v.y += a0.y; v.z += a0.z; v.w += a0.w;
            }
            if (f1) {
                const float4 a1 = s_acc[pair * 2 + 1][j];
                v.x += a1.x; v.y += a1.y; v.z += a1.z; v.w += a1.w;
            }
            v.x *= inv; v.y *= inv; v.z *= inv; v.w *= inv;
            __stcs(&op[j], v);
        }
    }
}

extern "C" void kernel_launch(void* const* d_in, const int* in_sizes, int n_in,
                              void* d_out, int out_size)
{
    const int* context = (const int*)d_in[0];
    const int* center  = (const int*)d_in[1];
    const float* W     = (const float*)d_in[2];
    for (int i = 0; i < n_in; i++) {
        if (in_sizes[i] == KB_B * KB_C)      context = (const int*)d_in[i];
        else if (in_sizes[i] == KB_B)        center  = (const int*)d_in[i];
        else if (in_sizes[i] > KB_B * KB_C)  W       = (const float*)d_in[i];
    }
    float* out = (float*)d_out;
    kre_kernel<<<KB_B / 2, NTHREADS>>>(context, center, W, out);
}